// round 7
// baseline (speedup 1.0000x reference)
#include <cuda_runtime.h>

#define BATCH 32
#define TSEQ  1024
#define DIN   256
#define UNITS 256
#define GC    2048   // 8*U total gate columns
#define G4    1024   // 4*U per direction

// ---------------- scratch (device globals; no runtime allocation) ------------
// xg layout: [t][col 0..2047][b]  (col = dir*1024 + gate*256 + unit)
__device__ float g_xg[TSEQ * GC * BATCH];            // 256 MB
__device__ float g_hist[TSEQ * 512 * BATCH];         // h history [t][dir*256+u][b], 64 MB
// arrival slots: one 128B line per (dir, unit-half); slot = cta&31. Stores only
// (no RMW serialization); poll warp reads the whole line in one wavefront.
__device__ __align__(128) unsigned g_slot[2][2][32];

// ---- PTX helpers -------------------------------------------------------------
#define CP_ASYNC16(dst_u32, src_ptr) \
    asm volatile("cp.async.cg.shared.global [%0], [%1], 16;" :: "r"(dst_u32), "l"(src_ptr))
#define CP_COMMIT() asm volatile("cp.async.commit_group;" ::: "memory")
#define CP_WAIT(n)  asm volatile("cp.async.wait_group %0;" :: "n"(n) : "memory")

__device__ __forceinline__ unsigned smem_u32(const void* p) {
    unsigned a;
    asm("{ .reg .u64 t; cvta.to.shared.u64 t, %1; cvt.u32.u64 %0, t; }" : "=r"(a) : "l"(p));
    return a;
}
__device__ __forceinline__ float fast_tanh(float x) {
    float r;
    asm("tanh.approx.f32 %0, %1;" : "=f"(r) : "f"(x));
    return r;
}

// ---------------- input projection GEMM: xg = x @ kernel ---------------------
// M = 32768 rows (r = t*32 + b), N = 2048, K = 256. Tiles 128x128x16.
__global__ void __launch_bounds__(256, 2) gemm_xg(const float* __restrict__ x,
                                                  const float* __restrict__ Wk) {
    __shared__ float As[16][132];   // [k][m], padded
    __shared__ float Bs[16][128];   // [k][n]

    const int tid = threadIdx.x;
    // reset rec arrival slots for this launch (rec runs after gemm completes)
    if (blockIdx.x == 0 && blockIdx.y == 0 && tid < 128)
        ((unsigned*)g_slot)[tid] = 0u;

    const int tx = tid & 15;        // n micro index
    const int ty = tid >> 4;        // m micro index
    const int n0 = blockIdx.x * 128;
    const int t0 = blockIdx.y * 4;  // 4 time steps * 32 batch = 128 rows

    unsigned long long acc2[8][4];  // acc2[i][jq] = {acc[i][2jq], acc[i][2jq+1]}
#pragma unroll
    for (int i = 0; i < 8; i++)
#pragma unroll
        for (int j = 0; j < 4; j++) acc2[i][j] = 0ull;

    for (int k0 = 0; k0 < DIN; k0 += 16) {
#pragma unroll
        for (int r = 0; r < 2; r++) {
            int idx = tid * 2 + r;              // 0..511
            int mloc = idx >> 2;                // 0..127
            int kq = idx & 3;
            int b = mloc & 31, tloc = mloc >> 5;
            float4 v = *(const float4*)&x[b * (TSEQ * DIN) + (t0 + tloc) * DIN + k0 + kq * 4];
            As[kq * 4 + 0][mloc] = v.x;
            As[kq * 4 + 1][mloc] = v.y;
            As[kq * 4 + 2][mloc] = v.z;
            As[kq * 4 + 3][mloc] = v.w;
        }
#pragma unroll
        for (int r = 0; r < 2; r++) {
            int idx = tid * 2 + r;              // 0..511
            int kk = idx >> 5;                  // 0..15
            int cq = idx & 31;
            *(float4*)&Bs[kk][cq * 4] = *(const float4*)&Wk[(k0 + kk) * GC + n0 + cq * 4];
        }
        __syncthreads();
#pragma unroll
        for (int k = 0; k < 16; k++) {
            float a[8];
            *(float4*)&a[0] = *(const float4*)&As[k][ty * 8];
            *(float4*)&a[4] = *(const float4*)&As[k][ty * 8 + 4];
            ulonglong2 bb0 = *(const ulonglong2*)&Bs[k][tx * 8];
            ulonglong2 bb1 = *(const ulonglong2*)&Bs[k][tx * 8 + 4];
            unsigned long long bv0 = bb0.x, bv1 = bb0.y, bv2 = bb1.x, bv3 = bb1.y;
#pragma unroll
            for (int i = 0; i < 8; i++) {
                unsigned long long a2;
                asm("mov.b64 %0, {%1, %1};" : "=l"(a2) : "f"(a[i]));
                asm("fma.rn.f32x2 %0, %1, %2, %0;" : "+l"(acc2[i][0]) : "l"(a2), "l"(bv0));
                asm("fma.rn.f32x2 %0, %1, %2, %0;" : "+l"(acc2[i][1]) : "l"(a2), "l"(bv1));
                asm("fma.rn.f32x2 %0, %1, %2, %0;" : "+l"(acc2[i][2]) : "l"(a2), "l"(bv2));
                asm("fma.rn.f32x2 %0, %1, %2, %0;" : "+l"(acc2[i][3]) : "l"(a2), "l"(bv3));
            }
        }
        __syncthreads();
    }
#pragma unroll
    for (int i = 0; i < 8; i++) {
        int mloc = ty * 8 + i;
        int b = mloc & 31, tloc = mloc >> 5;
        int t = t0 + tloc;
        float* orow = &g_xg[((size_t)t * GC + n0 + tx * 8) * BATCH + b];
#pragma unroll
        for (int jq = 0; jq < 4; jq++) {
            float lo, hi;
            asm("mov.b64 {%0, %1}, %2;" : "=f"(lo), "=f"(hi) : "l"(acc2[i][jq]));
            orow[(size_t)(2 * jq + 0) * BATCH] = lo;
            orow[(size_t)(2 * jq + 1) * BATCH] = hi;
        }
    }
}

// ---------------- persistent recurrent scan ----------------------------------
// 128 CTAs (64 per direction), 256 threads (8 warps) each. CTA owns 4 units.
// warp w: wu = w&3 -> unit offset, kh = w>>2 -> k-half. lane = batch.
// CTAs 0-31 of a direction produce units 0-127 (k-half 0), CTAs 32-63 produce
// units 128-255 (k-half 1). Arrival = st.release to a per-CTA slot in the
// producer half's 128B line; each kh-group's lead warp polls its producer
// line with one warp-wide acquire load + ballot.
__global__ void __launch_bounds__(256, 1) blstm_rec(const float* __restrict__ rk) {
    __shared__ float Ws[UNITS * 16];      // [k][wu*4+g] : 16 KB
    __shared__ float hs[UNITS * BATCH];   // [k][b]      : 32 KB (total 48 KB)
    // reduction partials alias hs[0..255] (k=0..7 of half 0); consumed in the
    // same step before kh=0's next staging overwrites them.
    ulonglong2* red_s = (ulonglong2*)hs;

    const int tid  = threadIdx.x;
    const int lane = tid & 31;            // batch b
    const int w    = tid >> 5;            // warp 0..7
    const int wu   = w & 3;               // unit offset 0..3
    const int kh   = w >> 2;              // k-half this warp consumes
    const int gtid = tid & 127;           // thread id within kh-group
    const int dir  = blockIdx.x >> 6;
    const int cta  = blockIdx.x & 63;
    const int u0   = cta * 4;
    const int u    = u0 + wu;
    const int half_mine = cta >> 5;       // unit-half this CTA produces

    // Ws[k*16 + wu*4 + g] = rk[k][dir*1024 + g*256 + u0+wu]
    for (int i = tid; i < UNITS * 16; i += 256) {
        int k = i >> 4, c = i & 15;
        int cu = c >> 2, g = c & 3;
        Ws[i] = rk[k * GC + dir * G4 + g * UNITS + u0 + cu];
    }
    for (int i = tid; i < (UNITS * BATCH) / 4; i += 256)
        ((float4*)hs)[i] = make_float4(0.f, 0.f, 0.f, 0.f);
    __syncthreads();

    const unsigned hs_base = smem_u32(hs);
    const ulonglong2* Ws2 = (const ulonglong2*)Ws;
    unsigned* my_slot   = &g_slot[dir][half_mine][cta & 31];
    unsigned* poll_addr = &g_slot[dir][kh][lane];     // lead warp reads whole line
    float c_state = 0.f;
    int tprev = 0;

    for (int s = 0; s < TSEQ; s++) {
        const int t = dir ? (TSEQ - 1 - s) : s;

        // gate-bias DRAM loads first (consumed ~2000 cyc later)
        float bi, bf, bm, bo;
        if (kh == 0) {
            const float* xgp = &g_xg[((size_t)t * GC + dir * G4) * BATCH];
            bi = __ldcs(&xgp[(0 * UNITS + u) * BATCH + lane]);
            bf = __ldcs(&xgp[(1 * UNITS + u) * BATCH + lane]);
            bm = __ldcs(&xgp[(2 * UNITS + u) * BATCH + lane]);
            bo = __ldcs(&xgp[(3 * UNITS + u) * BATCH + lane]);
        }

        if (s > 0) {
            // lead warp of each kh-group polls its producer half's slot line
            if (w == kh * 4) {
                const unsigned tgt = (unsigned)s;
                unsigned v;
                bool ok;
                do {
                    asm volatile("ld.acquire.gpu.global.u32 %0, [%1];"
                                 : "=r"(v) : "l"(poll_addr) : "memory");
                    ok = __all_sync(0xffffffffu, v >= tgt);
                    if (!ok) __nanosleep(20);
                } while (!ok);
            }
            asm volatile("bar.sync %0, 128;" :: "r"(1 + kh) : "memory");

            // stage this group's 16KB half (8 x 16B per thread)
            const float* src = &g_hist[((size_t)tprev * 512 + dir * 256) * BATCH] + (kh << 12);
            const unsigned dst0 = hs_base + ((unsigned)kh << 14);
#pragma unroll
            for (int j = 0; j < 8; j++)
                CP_ASYNC16(dst0 + (unsigned)(gtid + j * 128) * 16u, src + (gtid + j * 128) * 4);
            CP_COMMIT();
            CP_WAIT(0);
            asm volatile("bar.sync %0, 128;" :: "r"(1 + kh) : "memory");
        }

        // half-dot: k in [kh*128, kh*128+128)
        unsigned long long aif = 0ull, amo = 0ull;   // packed (i,f),(m,o) fp32x2
        const int kbase = kh << 7;
#pragma unroll 8
        for (int k = 0; k < 128; k++) {
            ulonglong2 wv = Ws2[(kbase + k) * 4 + wu];   // broadcast LDS.128
            float hv = hs[(kbase + k) * 32 + lane];      // conflict-free LDS.32
            unsigned long long h2;
            asm("mov.b64 %0, {%1, %1};" : "=l"(h2) : "f"(hv));
            asm("fma.rn.f32x2 %0, %1, %2, %0;" : "+l"(aif) : "l"(wv.x), "l"(h2));
            asm("fma.rn.f32x2 %0, %1, %2, %0;" : "+l"(amo) : "l"(wv.y), "l"(h2));
        }
        __syncthreads();            // all dot reads of hs complete
        if (kh == 1) {
            red_s[wu * 32 + lane] = make_ulonglong2(aif, amo);
        }
        __syncthreads();            // red_s visible

        if (kh == 0) {
            ulonglong2 p = red_s[wu * 32 + lane];
            asm("add.rn.f32x2 %0, %0, %1;" : "+l"(aif) : "l"(p.x));
            asm("add.rn.f32x2 %0, %0, %1;" : "+l"(amo) : "l"(p.y));
            float ai, af, am, ao;
            asm("mov.b64 {%0, %1}, %2;" : "=f"(ai), "=f"(af) : "l"(aif));
            asm("mov.b64 {%0, %1}, %2;" : "=f"(am), "=f"(ao) : "l"(amo));
            ai += bi; af += bf; am += bm; ao += bo;

            float gi = __saturatef(0.2f * ai + 0.5f);
            float gf = __saturatef(0.2f * af + 0.5f);
            float gm = fast_tanh(am);
            float go = __saturatef(0.2f * ao + 0.5f);
            c_state = gf * c_state + gi * gm;
            float h = go * fast_tanh(c_state);

            g_hist[((size_t)t * 512 + dir * 256 + u) * BATCH + lane] = h;   // coalesced

            // kh0-group barrier orders all 4 unit-warps' h stores, then arrive
            asm volatile("bar.sync 3, 128;" ::: "memory");
            if (tid == 0)
                asm volatile("st.release.gpu.global.u32 [%0], %1;"
                             :: "l"(my_slot), "r"((unsigned)(s + 1)) : "memory");
        }
        __syncthreads();
        tprev = t;
    }
}

// ---------------- final transpose: out[b][t][c] = hist[t][c][b] --------------
__global__ void __launch_bounds__(256) transpose_out(float* __restrict__ out) {
    __shared__ float S[128 * 33];
    const int t  = blockIdx.x;        // 0..1023
    const int c0 = blockIdx.y * 128;  // 0..3 * 128
    const int tid = threadIdx.x;

    const float* src = &g_hist[((size_t)t * 512 + c0) * BATCH];
#pragma unroll
    for (int i = 0; i < 4; i++) {
        int idx4 = tid + i * 256;                 // 0..1023 float4s
        float4 v = ((const float4*)src)[idx4];
        int e = idx4 * 4;
        int c = e >> 5, b0 = e & 31;
        float* d = &S[c * 33 + b0];
        d[0] = v.x; d[1] = v.y; d[2] = v.z; d[3] = v.w;
    }
    __syncthreads();

    const int lane = tid & 31;   // c quad index
    const int bq   = tid >> 5;   // 0..7
#pragma unroll
    for (int i = 0; i < 4; i++) {
        int b = bq + i * 8;
        int cc = lane * 4;
        float4 v = make_float4(S[(cc + 0) * 33 + b], S[(cc + 1) * 33 + b],
                               S[(cc + 2) * 33 + b], S[(cc + 3) * 33 + b]);
        *(float4*)&out[((size_t)b * TSEQ + t) * 512 + c0 + cc] = v;
    }
}

// ---------------- entry ------------------------------------------------------
extern "C" void kernel_launch(void* const* d_in, const int* in_sizes, int n_in,
                              void* d_out, int out_size) {
    (void)in_sizes; (void)n_in; (void)out_size;
    const float* x    = (const float*)d_in[0];   // [32,1024,256]
    const float* kern = (const float*)d_in[1];   // [256,2048]
    const float* rk   = (const float*)d_in[2];   // [256,2048]
    float* out = (float*)d_out;                  // [32,1024,512]

    dim3 ggrid(GC / 128, (BATCH * TSEQ) / 128);  // (16, 256)
    gemm_xg<<<ggrid, 256>>>(x, kern);
    blstm_rec<<<128, 256>>>(rk);
    dim3 tgrid(TSEQ, 4);
    transpose_out<<<tgrid, 256>>>(out);
}

// round 9
// speedup vs baseline: 2.1385x; 2.1385x over previous
#include <cuda_runtime.h>
#include <cuda_bf16.h>
#include <cstdint>

#define BATCH 32
#define TSEQ  1024
#define DIN   256
#define UNITS 256
#define GC    2048   // 8*U total gate columns
#define G4    1024   // 4*U per direction

// ---------------- scratch (device globals; no runtime allocation) ------------
__device__ float g_xg[TSEQ * GC * BATCH];            // 256 MB, [t][col][b]
__device__ float g_hist[TSEQ * 512 * BATCH];         // h history [t][dir*256+u][b]
__device__ unsigned int g_cnt[64];                   // per-direction barrier counters

// ---- PTX helpers -------------------------------------------------------------
#define CP_ASYNC16(dst_u32, src_ptr) \
    asm volatile("cp.async.cg.shared.global [%0], [%1], 16;" :: "r"(dst_u32), "l"(src_ptr))
#define CP_COMMIT() asm volatile("cp.async.commit_group;" ::: "memory")
#define CP_WAIT(n)  asm volatile("cp.async.wait_group %0;" :: "n"(n) : "memory")

__device__ __forceinline__ unsigned smem_u32(const void* p) {
    unsigned a;
    asm("{ .reg .u64 t; cvta.to.shared.u64 t, %1; cvt.u32.u64 %0, t; }" : "=r"(a) : "l"(p));
    return a;
}
__device__ __forceinline__ float fast_tanh(float x) {
    float r;
    asm("tanh.approx.f32 %0, %1;" : "=f"(r) : "f"(x));
    return r;
}

#define LDSM_X4(r, addr) \
    asm volatile("ldmatrix.sync.aligned.m8n8.x4.shared.b16 {%0,%1,%2,%3}, [%4];" \
                 : "=r"((r)[0]), "=r"((r)[1]), "=r"((r)[2]), "=r"((r)[3]) : "r"(addr))

#define MMA_BF16(d, a, b0, b1) \
    asm volatile("mma.sync.aligned.m16n8k16.row.col.f32.bf16.bf16.f32 " \
                 "{%0,%1,%2,%3}, {%4,%5,%6,%7}, {%8,%9}, {%0,%1,%2,%3};" \
                 : "+f"((d)[0]), "+f"((d)[1]), "+f"((d)[2]), "+f"((d)[3]) \
                 : "r"((a)[0]), "r"((a)[1]), "r"((a)[2]), "r"((a)[3]), \
                   "r"(b0), "r"(b1))

// split fp32 pair -> (hi, lo) bf16x2
__device__ __forceinline__ void cvt_split2(float2 f, uint32_t& h, uint32_t& l) {
    __nv_bfloat162 h2 = __float22bfloat162_rn(f);
    float2 hf = __bfloat1622float2(h2);
    __nv_bfloat162 l2 = __float22bfloat162_rn(make_float2(f.x - hf.x, f.y - hf.y));
    h = *(uint32_t*)&h2;
    l = *(uint32_t*)&l2;
}

// ---------------- tensor-core input projection: xg = x @ kernel --------------
// M = 32768 (m = t*32 + b), N = 2048, K = 256. CTA tile 128Mx128N, 8 warps,
// warp tile 32Mx64N, K in 8 chunks of 32. bf16 3-term split via HMMA
// (mma.sync m16n8k16), fp32 accumulation in registers.
#define LDA 40   // smem leading dim in bf16 elems (80B rows, 16B aligned, LDSM conflict-free)

__global__ void __launch_bounds__(256, 2) gemm_mma(const float* __restrict__ x,
                                                   const float* __restrict__ Wk) {
    __shared__ __align__(16) __nv_bfloat16 Ah[128 * LDA];
    __shared__ __align__(16) __nv_bfloat16 Al[128 * LDA];
    __shared__ __align__(16) __nv_bfloat16 Bh[128 * LDA];
    __shared__ __align__(16) __nv_bfloat16 Bl[128 * LDA];

    const int tid = threadIdx.x;
    if (blockIdx.x == 0 && blockIdx.y == 0 && tid < 64) g_cnt[tid] = 0u;

    const int w    = tid >> 5;
    const int lane = tid & 31;
    const int warp_m = (w & 3) * 32;
    const int warp_n = (w >> 2) * 64;
    const int n0 = blockIdx.x * 128;
    const int t0 = blockIdx.y * 4;          // 4 timesteps x 32 batch = 128 M rows

    const uint32_t ah_s = smem_u32(Ah), al_s = smem_u32(Al);
    const uint32_t bh_s = smem_u32(Bh), bl_s = smem_u32(Bl);

    float acc[2][8][4];
#pragma unroll
    for (int mt = 0; mt < 2; mt++)
#pragma unroll
        for (int nf = 0; nf < 8; nf++)
#pragma unroll
            for (int q = 0; q < 4; q++) acc[mt][nf][q] = 0.f;

    // LDSM lane addressing (constant across chunks)
    const int a_r  = lane & 15;             // A row within 16
    const int a_c8 = (lane >> 4) * 8;       // A col half
    const int b_nr = (lane & 7) + ((lane >> 4) & 1) * 8;  // B n-row within 16
    const int b_k8 = ((lane >> 3) & 1) * 8;               // B k half

    for (int kc = 0; kc < DIN; kc += 32) {
        // ---- stage A: x[m][kc..kc+31] -> (Ah, Al), row-major [m][k]
#pragma unroll
        for (int i = 0; i < 4; i++) {
            int idx = tid + i * 256;        // 0..1023
            int mloc = idx >> 3, q = idx & 7;
            const float* src = &x[((size_t)(mloc & 31) * TSEQ + t0 + (mloc >> 5)) * DIN + kc + q * 4];
            float4 v = *(const float4*)src;
            uint32_t h01, l01, h23, l23;
            cvt_split2(make_float2(v.x, v.y), h01, l01);
            cvt_split2(make_float2(v.z, v.w), h23, l23);
            int o = mloc * LDA + q * 4;
            *(uint32_t*)&Ah[o] = h01; *(uint32_t*)&Ah[o + 2] = h23;
            *(uint32_t*)&Al[o] = l01; *(uint32_t*)&Al[o + 2] = l23;
        }
        // ---- stage B: W[kc+kk][n0+n] -> (Bh, Bl) transposed to [n][k]
#pragma unroll
        for (int i = 0; i < 4; i++) {
            int idx = tid + i * 256;        // 0..1023
            int kk = idx >> 5, nq = idx & 31;
            const float* src = &Wk[(size_t)(kc + kk) * GC + n0 + nq * 4];
            float4 v = *(const float4*)src;
            float f[4] = {v.x, v.y, v.z, v.w};
#pragma unroll
            for (int j = 0; j < 4; j++) {
                __nv_bfloat16 hb = __float2bfloat16_rn(f[j]);
                __nv_bfloat16 lb = __float2bfloat16_rn(f[j] - __bfloat162float(hb));
                int o = (nq * 4 + j) * LDA + kk;
                Bh[o] = hb;
                Bl[o] = lb;
            }
        }
        __syncthreads();

#pragma unroll
        for (int ks = 0; ks < 2; ks++) {
            const int k0 = ks * 16;
            uint32_t afh[2][4], afl[2][4];
#pragma unroll
            for (int mt = 0; mt < 2; mt++) {
                uint32_t off = (uint32_t)((warp_m + mt * 16 + a_r) * LDA + k0 + a_c8) * 2u;
                LDSM_X4(afh[mt], ah_s + off);
                LDSM_X4(afl[mt], al_s + off);
            }
            uint32_t bf[4][4];
            // Bh terms: Ah*Bh and Al*Bh
#pragma unroll
            for (int bt = 0; bt < 4; bt++) {
                uint32_t off = (uint32_t)((warp_n + bt * 16 + b_nr) * LDA + k0 + b_k8) * 2u;
                LDSM_X4(bf[bt], bh_s + off);
            }
#pragma unroll
            for (int mt = 0; mt < 2; mt++)
#pragma unroll
                for (int bt = 0; bt < 4; bt++) {
                    MMA_BF16(acc[mt][bt * 2],     afh[mt], bf[bt][0], bf[bt][1]);
                    MMA_BF16(acc[mt][bt * 2 + 1], afh[mt], bf[bt][2], bf[bt][3]);
                    MMA_BF16(acc[mt][bt * 2],     afl[mt], bf[bt][0], bf[bt][1]);
                    MMA_BF16(acc[mt][bt * 2 + 1], afl[mt], bf[bt][2], bf[bt][3]);
                }
            // Bl term: Ah*Bl
#pragma unroll
            for (int bt = 0; bt < 4; bt++) {
                uint32_t off = (uint32_t)((warp_n + bt * 16 + b_nr) * LDA + k0 + b_k8) * 2u;
                LDSM_X4(bf[bt], bl_s + off);
            }
#pragma unroll
            for (int mt = 0; mt < 2; mt++)
#pragma unroll
                for (int bt = 0; bt < 4; bt++) {
                    MMA_BF16(acc[mt][bt * 2],     afh[mt], bf[bt][0], bf[bt][1]);
                    MMA_BF16(acc[mt][bt * 2 + 1], afh[mt], bf[bt][2], bf[bt][3]);
                }
        }
        __syncthreads();
    }

    // ---- epilogue: scatter to g_xg[t][col][b]
#pragma unroll
    for (int mt = 0; mt < 2; mt++) {
        int m0 = warp_m + mt * 16 + (lane >> 2);   // rows m0 and m0+8
        int m1 = m0 + 8;
        int ta = t0 + (m0 >> 5), ba = m0 & 31;
        int tb = t0 + (m1 >> 5), bb = m1 & 31;
#pragma unroll
        for (int nf = 0; nf < 8; nf++) {
            int n = n0 + warp_n + nf * 8 + (lane & 3) * 2;
            float* pa = &g_xg[((size_t)ta * GC + n) * BATCH + ba];
            float* pb = &g_xg[((size_t)tb * GC + n) * BATCH + bb];
            pa[0]     = acc[mt][nf][0];
            pa[BATCH] = acc[mt][nf][1];
            pb[0]     = acc[mt][nf][2];
            pb[BATCH] = acc[mt][nf][3];
        }
    }
}

// ---------------- persistent recurrent scan (R5 best: DO NOT TOUCH) ----------
__global__ void __launch_bounds__(256, 1) blstm_rec(const float* __restrict__ rk) {
    __shared__ float Ws[UNITS * 16];      // [k][wu*4+g] : 16 KB
    __shared__ float hs[UNITS * BATCH];   // [k][b]      : 32 KB
    ulonglong2* red_s = (ulonglong2*)hs;

    const int tid  = threadIdx.x;
    const int lane = tid & 31;            // batch b
    const int w    = tid >> 5;            // warp 0..7
    const int wu   = w & 3;               // unit offset 0..3
    const int kh   = w >> 2;              // k-half 0/1
    const int gtid = tid & 127;           // thread id within kh-group
    const int dir  = blockIdx.x >> 6;
    const int cta  = blockIdx.x & 63;
    const int u0   = cta * 4;
    const int u    = u0 + wu;

    for (int i = tid; i < UNITS * 16; i += 256) {
        int k = i >> 4, c = i & 15;
        int cu = c >> 2, g = c & 3;
        Ws[i] = rk[k * GC + dir * G4 + g * UNITS + u0 + cu];
    }
    for (int i = tid; i < (UNITS * BATCH) / 4; i += 256)
        ((float4*)hs)[i] = make_float4(0.f, 0.f, 0.f, 0.f);
    __syncthreads();

    const unsigned hs_base = smem_u32(hs);
    const ulonglong2* Ws2 = (const ulonglong2*)Ws;
    unsigned int* cnt = &g_cnt[dir * 32];
    float c_state = 0.f;
    int tprev = 0;

    for (int s = 0; s < TSEQ; s++) {
        const int t = dir ? (TSEQ - 1 - s) : s;

        float bi, bf, bm, bo;
        if (kh == 0) {
            const float* xgp = &g_xg[((size_t)t * GC + dir * G4) * BATCH];
            bi = __ldcs(&xgp[(0 * UNITS + u) * BATCH + lane]);
            bf = __ldcs(&xgp[(1 * UNITS + u) * BATCH + lane]);
            bm = __ldcs(&xgp[(2 * UNITS + u) * BATCH + lane]);
            bo = __ldcs(&xgp[(3 * UNITS + u) * BATCH + lane]);
        }

        if (s > 0) {
            const float* src = &g_hist[((size_t)tprev * 512 + dir * 256) * BATCH] + (kh << 12);
            const unsigned dst0 = hs_base + ((unsigned)kh << 14);
#pragma unroll
            for (int j = 0; j < 8; j++)
                CP_ASYNC16(dst0 + (unsigned)(gtid + j * 128) * 16u, src + (gtid + j * 128) * 4);
            CP_COMMIT();
            CP_WAIT(0);
            asm volatile("bar.sync %0, 128;" :: "r"(1 + kh) : "memory");
        }

        unsigned long long aif = 0ull, amo = 0ull;
        const int kbase = kh << 7;
#pragma unroll 8
        for (int k = 0; k < 128; k++) {
            ulonglong2 wv = Ws2[(kbase + k) * 4 + wu];
            float hv = hs[(kbase + k) * 32 + lane];
            unsigned long long h2;
            asm("mov.b64 %0, {%1, %1};" : "=l"(h2) : "f"(hv));
            asm("fma.rn.f32x2 %0, %1, %2, %0;" : "+l"(aif) : "l"(wv.x), "l"(h2));
            asm("fma.rn.f32x2 %0, %1, %2, %0;" : "+l"(amo) : "l"(wv.y), "l"(h2));
        }
        __syncthreads();
        if (kh == 1) {
            red_s[wu * 32 + lane] = make_ulonglong2(aif, amo);
        }
        __syncthreads();

        if (kh == 0) {
            ulonglong2 p = red_s[wu * 32 + lane];
            asm("add.rn.f32x2 %0, %0, %1;" : "+l"(aif) : "l"(p.x));
            asm("add.rn.f32x2 %0, %0, %1;" : "+l"(amo) : "l"(p.y));
            float ai, af, am, ao;
            asm("mov.b64 {%0, %1}, %2;" : "=f"(ai), "=f"(af) : "l"(aif));
            asm("mov.b64 {%0, %1}, %2;" : "=f"(am), "=f"(ao) : "l"(amo));
            ai += bi; af += bf; am += bm; ao += bo;

            float gi = __saturatef(0.2f * ai + 0.5f);
            float gf = __saturatef(0.2f * af + 0.5f);
            float gm = fast_tanh(am);
            float go = __saturatef(0.2f * ao + 0.5f);
            c_state = gf * c_state + gi * gm;
            float h = go * fast_tanh(c_state);

            g_hist[((size_t)t * 512 + dir * 256 + u) * BATCH + lane] = h;
        }

        __syncthreads();
        if (tid == 0) {
            asm volatile("red.release.gpu.global.add.u32 [%0], 1;" :: "l"(cnt) : "memory");
            const unsigned target = (unsigned)(s + 1) * 64u;
            unsigned v;
            asm volatile("ld.acquire.gpu.global.u32 %0, [%1];" : "=r"(v) : "l"(cnt) : "memory");
            while (v < target) {
                __nanosleep(32);
                asm volatile("ld.acquire.gpu.global.u32 %0, [%1];" : "=r"(v) : "l"(cnt) : "memory");
            }
        }
        __syncthreads();
        tprev = t;
    }
}

// ---------------- final transpose: out[b][t][c] = hist[t][c][b] --------------
__global__ void __launch_bounds__(256) transpose_out(float* __restrict__ out) {
    __shared__ float S[128 * 33];
    const int t  = blockIdx.x;
    const int c0 = blockIdx.y * 128;
    const int tid = threadIdx.x;

    const float* src = &g_hist[((size_t)t * 512 + c0) * BATCH];
#pragma unroll
    for (int i = 0; i < 4; i++) {
        int idx4 = tid + i * 256;
        float4 v = ((const float4*)src)[idx4];
        int e = idx4 * 4;
        int c = e >> 5, b0 = e & 31;
        float* d = &S[c * 33 + b0];
        d[0] = v.x; d[1] = v.y; d[2] = v.z; d[3] = v.w;
    }
    __syncthreads();

    const int lane = tid & 31;
    const int bq   = tid >> 5;
#pragma unroll
    for (int i = 0; i < 4; i++) {
        int b = bq + i * 8;
        int cc = lane * 4;
        float4 v = make_float4(S[(cc + 0) * 33 + b], S[(cc + 1) * 33 + b],
                               S[(cc + 2) * 33 + b], S[(cc + 3) * 33 + b]);
        *(float4*)&out[((size_t)b * TSEQ + t) * 512 + c0 + cc] = v;
    }
}

// ---------------- entry ------------------------------------------------------
extern "C" void kernel_launch(void* const* d_in, const int* in_sizes, int n_in,
                              void* d_out, int out_size) {
    (void)in_sizes; (void)n_in; (void)out_size;
    const float* x    = (const float*)d_in[0];   // [32,1024,256]
    const float* kern = (const float*)d_in[1];   // [256,2048]
    const float* rk   = (const float*)d_in[2];   // [256,2048]
    float* out = (float*)d_out;                  // [32,1024,512]

    dim3 ggrid(GC / 128, (BATCH * TSEQ) / 128);  // (16, 256)
    gemm_mma<<<ggrid, 256>>>(x, kern);
    blstm_rec<<<128, 256>>>(rk);
    dim3 tgrid(TSEQ, 4);
    transpose_out<<<tgrid, 256>>>(out);
}

// round 10
// speedup vs baseline: 2.5677x; 1.2007x over previous
#include <cuda_runtime.h>
#include <cuda_bf16.h>
#include <cstdint>

#define BATCH 32
#define TSEQ  1024
#define DIN   256
#define UNITS 256
#define GC    2048   // 8*U total gate columns
#define G4    1024   // 4*U per direction
#define LDH   80     // padded hs row stride in bytes (32 bf16 = 64B data + 16B pad)

// ---------------- scratch (device globals; no runtime allocation) ------------
__device__ float g_xg[TSEQ * GC * BATCH];            // 256 MB, [t][col][b]
__device__ float g_hist[TSEQ * 512 * BATCH];         // h history fp32 [t][dir*256+u][b]
__device__ __nv_bfloat16 g_hbf[TSEQ * 2 * 2 * 256 * 32];  // [t][dir][mat hi/lo][u][b], 64 MB
__device__ unsigned int g_cnt[64];                   // per-direction barrier counters

// ---- PTX helpers -------------------------------------------------------------
#define CP_ASYNC16(dst_u32, src_ptr) \
    asm volatile("cp.async.cg.shared.global [%0], [%1], 16;" :: "r"(dst_u32), "l"(src_ptr))
#define CP_COMMIT() asm volatile("cp.async.commit_group;" ::: "memory")
#define CP_WAIT(n)  asm volatile("cp.async.wait_group %0;" :: "n"(n) : "memory")

__device__ __forceinline__ unsigned smem_u32(const void* p) {
    unsigned a;
    asm("{ .reg .u64 t; cvta.to.shared.u64 t, %1; cvt.u32.u64 %0, t; }" : "=r"(a) : "l"(p));
    return a;
}
__device__ __forceinline__ float fast_tanh(float x) {
    float r;
    asm("tanh.approx.f32 %0, %1;" : "=f"(r) : "f"(x));
    return r;
}

#define LDSM_X4(r, addr) \
    asm volatile("ldmatrix.sync.aligned.m8n8.x4.shared.b16 {%0,%1,%2,%3}, [%4];" \
                 : "=r"((r)[0]), "=r"((r)[1]), "=r"((r)[2]), "=r"((r)[3]) : "r"(addr))
#define LDSM_X4T(r, addr) \
    asm volatile("ldmatrix.sync.aligned.m8n8.x4.trans.shared.b16 {%0,%1,%2,%3}, [%4];" \
                 : "=r"((r)[0]), "=r"((r)1[0]), "=r"((r)[2]), "=r"((r)[3]) : "r"(addr))
// (typo-proof real macro below)
#undef LDSM_X4T
#define LDSM_X4T(r, addr) \
    asm volatile("ldmatrix.sync.aligned.m8n8.x4.trans.shared.b16 {%0,%1,%2,%3}, [%4];" \
                 : "=r"((r)[0]), "=r"((r)[1]), "=r"((r)[2]), "=r"((r)[3]) : "r"(addr))
#define LDSM_X2(r, addr) \
    asm volatile("ldmatrix.sync.aligned.m8n8.x2.shared.b16 {%0,%1}, [%2];" \
                 : "=r"((r)[0]), "=r"((r)[1]) : "r"(addr))

#define MMA_BF16(d, a, b0, b1) \
    asm volatile("mma.sync.aligned.m16n8k16.row.col.f32.bf16.bf16.f32 " \
                 "{%0,%1,%2,%3}, {%4,%5,%6,%7}, {%8,%9}, {%0,%1,%2,%3};" \
                 : "+f"((d)[0]), "+f"((d)[1]), "+f"((d)[2]), "+f"((d)[3]) \
                 : "r"((a)[0]), "r"((a)[1]), "r"((a)[2]), "r"((a)[3]), \
                   "r"(b0), "r"(b1))

// split fp32 pair -> (hi, lo) bf16x2
__device__ __forceinline__ void cvt_split2(float2 f, uint32_t& h, uint32_t& l) {
    __nv_bfloat162 h2 = __float22bfloat162_rn(f);
    float2 hf = __bfloat1622float2(h2);
    __nv_bfloat162 l2 = __float22bfloat162_rn(make_float2(f.x - hf.x, f.y - hf.y));
    h = *(uint32_t*)&h2;
    l = *(uint32_t*)&l2;
}

// ---------------- tensor-core input projection: xg = x @ kernel --------------
// (unchanged from R9 best: 682us, L1-bound)
#define LDA 40

__global__ void __launch_bounds__(256, 2) gemm_mma(const float* __restrict__ x,
                                                   const float* __restrict__ Wk) {
    __shared__ __align__(16) __nv_bfloat16 Ah[128 * LDA];
    __shared__ __align__(16) __nv_bfloat16 Al[128 * LDA];
    __shared__ __align__(16) __nv_bfloat16 Bh[128 * LDA];
    __shared__ __align__(16) __nv_bfloat16 Bl[128 * LDA];

    const int tid = threadIdx.x;
    if (blockIdx.x == 0 && blockIdx.y == 0 && tid < 64) g_cnt[tid] = 0u;

    const int w    = tid >> 5;
    const int lane = tid & 31;
    const int warp_m = (w & 3) * 32;
    const int warp_n = (w >> 2) * 64;
    const int n0 = blockIdx.x * 128;
    const int t0 = blockIdx.y * 4;

    const uint32_t ah_s = smem_u32(Ah), al_s = smem_u32(Al);
    const uint32_t bh_s = smem_u32(Bh), bl_s = smem_u32(Bl);

    float acc[2][8][4];
#pragma unroll
    for (int mt = 0; mt < 2; mt++)
#pragma unroll
        for (int nf = 0; nf < 8; nf++)
#pragma unroll
            for (int q = 0; q < 4; q++) acc[mt][nf][q] = 0.f;

    const int a_r  = lane & 15;
    const int a_c8 = (lane >> 4) * 8;
    const int b_nr = (lane & 7) + ((lane >> 4) & 1) * 8;
    const int b_k8 = ((lane >> 3) & 1) * 8;

    for (int kc = 0; kc < DIN; kc += 32) {
#pragma unroll
        for (int i = 0; i < 4; i++) {
            int idx = tid + i * 256;
            int mloc = idx >> 3, q = idx & 7;
            const float* src = &x[((size_t)(mloc & 31) * TSEQ + t0 + (mloc >> 5)) * DIN + kc + q * 4];
            float4 v = *(const float4*)src;
            uint32_t h01, l01, h23, l23;
            cvt_split2(make_float2(v.x, v.y), h01, l01);
            cvt_split2(make_float2(v.z, v.w), h23, l23);
            int o = mloc * LDA + q * 4;
            *(uint32_t*)&Ah[o] = h01; *(uint32_t*)&Ah[o + 2] = h23;
            *(uint32_t*)&Al[o] = l01; *(uint32_t*)&Al[o + 2] = l23;
        }
#pragma unroll
        for (int i = 0; i < 4; i++) {
            int idx = tid + i * 256;
            int kk = idx >> 5, nq = idx & 31;
            const float* src = &Wk[(size_t)(kc + kk) * GC + n0 + nq * 4];
            float4 v = *(const float4*)src;
            float f[4] = {v.x, v.y, v.z, v.w};
#pragma unroll
            for (int j = 0; j < 4; j++) {
                __nv_bfloat16 hb = __float2bfloat16_rn(f[j]);
                __nv_bfloat16 lb = __float2bfloat16_rn(f[j] - __bfloat162float(hb));
                int o = (nq * 4 + j) * LDA + kk;
                Bh[o] = hb;
                Bl[o] = lb;
            }
        }
        __syncthreads();

#pragma unroll
        for (int ks = 0; ks < 2; ks++) {
            const int k0 = ks * 16;
            uint32_t afh[2][4], afl[2][4];
#pragma unroll
            for (int mt = 0; mt < 2; mt++) {
                uint32_t off = (uint32_t)((warp_m + mt * 16 + a_r) * LDA + k0 + a_c8) * 2u;
                LDSM_X4(afh[mt], ah_s + off);
                LDSM_X4(afl[mt], al_s + off);
            }
            uint32_t bfr[4][4];
#pragma unroll
            for (int bt = 0; bt < 4; bt++) {
                uint32_t off = (uint32_t)((warp_n + bt * 16 + b_nr) * LDA + k0 + b_k8) * 2u;
                LDSM_X4(bfr[bt], bh_s + off);
            }
#pragma unroll
            for (int mt = 0; mt < 2; mt++)
#pragma unroll
                for (int bt = 0; bt < 4; bt++) {
                    MMA_BF16(acc[mt][bt * 2],     afh[mt], bfr[bt][0], bfr[bt][1]);
                    MMA_BF16(acc[mt][bt * 2 + 1], afh[mt], bfr[bt][2], bfr[bt][3]);
                    MMA_BF16(acc[mt][bt * 2],     afl[mt], bfr[bt][0], bfr[bt][1]);
                    MMA_BF16(acc[mt][bt * 2 + 1], afl[mt], bfr[bt][2], bfr[bt][3]);
                }
#pragma unroll
            for (int bt = 0; bt < 4; bt++) {
                uint32_t off = (uint32_t)((warp_n + bt * 16 + b_nr) * LDA + k0 + b_k8) * 2u;
                LDSM_X4(bfr[bt], bl_s + off);
            }
#pragma unroll
            for (int mt = 0; mt < 2; mt++)
#pragma unroll
                for (int bt = 0; bt < 4; bt++) {
                    MMA_BF16(acc[mt][bt * 2],     afh[mt], bfr[bt][0], bfr[bt][1]);
                    MMA_BF16(acc[mt][bt * 2 + 1], afh[mt], bfr[bt][2], bfr[bt][3]);
                }
        }
        __syncthreads();
    }

#pragma unroll
    for (int mt = 0; mt < 2; mt++) {
        int m0 = warp_m + mt * 16 + (lane >> 2);
        int m1 = m0 + 8;
        int ta = t0 + (m0 >> 5), ba = m0 & 31;
        int tb = t0 + (m1 >> 5), bb = m1 & 31;
#pragma unroll
        for (int nf = 0; nf < 8; nf++) {
            int n = n0 + warp_n + nf * 8 + (lane & 3) * 2;
            float* pa = &g_xg[((size_t)ta * GC + n) * BATCH + ba];
            float* pb = &g_xg[((size_t)tb * GC + n) * BATCH + bb];
            pa[0]     = acc[mt][nf][0];
            pa[BATCH] = acc[mt][nf][1];
            pb[0]     = acc[mt][nf][2];
            pb[BATCH] = acc[mt][nf][3];
        }
    }
}

// ---------------- persistent recurrent scan: HMMA dot ------------------------
// 128 CTAs (64/dir), 256 threads. CTA owns 4 units (16 gate cols).
// warp w: kh = w>>2 (k-half), mh = (w>>1)&1 (batch half), nh = w&1 (col half).
// gates[32b x 16col] += h^T[32b x 256k] . W[256k x 16col] via mma.m16n8k16,
// bf16 3-term split. W fragments preloaded in registers; h staged as bf16
// (hi,lo) pair from g_hbf and read via ldmatrix.x4.trans. Barrier = R5 (fixed).
__global__ void __launch_bounds__(256, 1) blstm_rec(const float* __restrict__ rk) {
    // hs area: hi matrix [256][LDH] then lo matrix [256][LDH]; aliased by the
    // one-time W^T staging (2 x 16 x 528B) which is consumed before step 1.
    __shared__ __align__(16) char hs_area[2 * 256 * LDH];   // 40960 B
    __shared__ float Gs[2][16][33];                         // per-k-half gate partials

    const int tid  = threadIdx.x;
    const int lane = tid & 31;
    const int w    = tid >> 5;
    const int kh   = w >> 2;
    const int mh   = (w >> 1) & 1;
    const int nh   = w & 1;
    const int gtid = tid & 127;
    const int dir  = blockIdx.x >> 6;
    const int cta  = blockIdx.x & 63;
    const int u0   = cta * 4;

    // ---- one-time: build W^T (hi,lo) bf16 in smem, padded rows of 264 halves
    {
        __nv_bfloat16* Wh_sm = (__nv_bfloat16*)hs_area;
        __nv_bfloat16* Wl_sm = (__nv_bfloat16*)(hs_area + 8448);
        for (int i = tid; i < 16 * 256; i += 256) {
            int n = i >> 8, k = i & 255;        // n = cu*4+g
            float v = rk[(size_t)k * GC + dir * G4 + (n & 3) * 256 + u0 + (n >> 2)];
            __nv_bfloat16 hb = __float2bfloat16_rn(v);
            Wh_sm[n * 264 + k] = hb;
            Wl_sm[n * 264 + k] = __float2bfloat16_rn(v - __bfloat162float(hb));
        }
    }
    __syncthreads();

    // ---- preload B fragments (per warp: 8 ksteps x {hi,lo} x 2 regs)
    uint32_t bfh[8][2], bfl[8][2];
    {
        const uint32_t whb = smem_u32(hs_area);
        const uint32_t wlb = whb + 8448;
        int ln = lane & 15;
        uint32_t loff = (uint32_t)(nh * 8 + (ln & 7)) * 528u + ((ln >> 3) ? 16u : 0u)
                        + (uint32_t)kh * 256u;   // kh*128 k * 2B
#pragma unroll
        for (int ks = 0; ks < 8; ks++) {
            LDSM_X2(bfh[ks], whb + loff + ks * 32u);
            LDSM_X2(bfl[ks], wlb + loff + ks * 32u);
        }
    }
    __syncthreads();   // done reading W^T; hs_area free for staging

    // ---- A-fragment ldmatrix lane offsets (constant per step)
    const uint32_t hsH = smem_u32(hs_area);
    const uint32_t hsL = hsH + 256 * LDH;
    uint32_t a_loff;
    {
        int q = lane >> 3, i = lane & 7;
        int row = kh * 128 + (q >> 1) * 8 + i;           // k row
        int colb = (mh * 16 + (q & 1) * 8) * 2;          // batch col bytes
        a_loff = (uint32_t)row * LDH + (uint32_t)colb;
    }

    unsigned int* cnt = &g_cnt[dir * 32];
    float c_state = 0.f;
    int tprev = 0;

    for (int s = 0; s < TSEQ; s++) {
        const int t = dir ? (TSEQ - 1 - s) : s;

        // gate-bias DRAM loads (kh=0 warps: thread (wu=w, lane=b))
        float bi, bf_, bm, bo;
        if (kh == 0) {
            const float* xgp = &g_xg[((size_t)t * GC + dir * G4) * BATCH];
            bi  = __ldcs(&xgp[(0 * UNITS + u0 + w) * BATCH + lane]);
            bf_ = __ldcs(&xgp[(1 * UNITS + u0 + w) * BATCH + lane]);
            bm  = __ldcs(&xgp[(2 * UNITS + u0 + w) * BATCH + lane]);
            bo  = __ldcs(&xgp[(3 * UNITS + u0 + w) * BATCH + lane]);
        }

        float acc[4] = {0.f, 0.f, 0.f, 0.f};

        if (s > 0) {
            // stage this k-half of h (hi+lo) from g_hbf: 8KB per matrix per group
            const char* srcH = (const char*)g_hbf
                + (((size_t)tprev * 2 + dir) * 2 + 0) * 16384 + (size_t)kh * 8192;
            const char* srcL = srcH + 16384;
            const uint32_t dstH = hsH + (uint32_t)kh * 128u * LDH;
            const uint32_t dstL = hsL + (uint32_t)kh * 128u * LDH;
#pragma unroll
            for (int j = 0; j < 4; j++) {
                int c = gtid + j * 128;          // 0..511 16B-chunks
                int row = c >> 2, ch = c & 3;
                CP_ASYNC16(dstH + (uint32_t)row * LDH + ch * 16u, srcH + row * 64 + ch * 16);
            }
#pragma unroll
            for (int j = 0; j < 4; j++) {
                int c = gtid + j * 128;
                int row = c >> 2, ch = c & 3;
                CP_ASYNC16(dstL + (uint32_t)row * LDH + ch * 16u, srcL + row * 64 + ch * 16);
            }
            CP_COMMIT();
            CP_WAIT(0);
            asm volatile("bar.sync %0, 128;" :: "r"(1 + kh) : "memory");

            // 8 ksteps: 2 ldmatrix.trans + 3 MMA each
#pragma unroll
            for (int ks = 0; ks < 8; ks++) {
                uint32_t ah[4], al[4];
                LDSM_X4T(ah, hsH + a_loff + ks * (16u * LDH));
                LDSM_X4T(al, hsL + a_loff + ks * (16u * LDH));
                MMA_BF16(acc, ah, bfh[ks][0], bfh[ks][1]);
                MMA_BF16(acc, al, bfh[ks][0], bfh[ks][1]);
                MMA_BF16(acc, ah, bfl[ks][0], bfl[ks][1]);
            }
        }

        // write partials: Gs[kh][n][m]
        {
            int m0 = mh * 16 + (lane >> 2);
            int n0 = nh * 8 + (lane & 3) * 2;
            Gs[kh][n0][m0]         = acc[0];
            Gs[kh][n0 + 1][m0]     = acc[1];
            Gs[kh][n0][m0 + 8]     = acc[2];
            Gs[kh][n0 + 1][m0 + 8] = acc[3];
        }
        __syncthreads();

        // epilogue: kh=0 warps, thread (wu=w, lane=b)
        if (kh == 0) {
            float ai = Gs[0][w * 4 + 0][lane] + Gs[1][w * 4 + 0][lane] + bi;
            float af = Gs[0][w * 4 + 1][lane] + Gs[1][w * 4 + 1][lane] + bf_;
            float am = Gs[0][w * 4 + 2][lane] + Gs[1][w * 4 + 2][lane] + bm;
            float ao = Gs[0][w * 4 + 3][lane] + Gs[1][w * 4 + 3][lane] + bo;

            float gi = __saturatef(0.2f * ai + 0.5f);
            float gf = __saturatef(0.2f * af + 0.5f);
            float gm = fast_tanh(am);
            float go = __saturatef(0.2f * ao + 0.5f);
            c_state = gf * c_state + gi * gm;
            float h = go * fast_tanh(c_state);

            const int u = u0 + w;
            g_hist[((size_t)t * 512 + dir * 256 + u) * BATCH + lane] = h;
            __nv_bfloat16 hh = __float2bfloat16_rn(h);
            __nv_bfloat16 hl = __float2bfloat16_rn(h - __bfloat162float(hh));
            size_t hb = (((size_t)t * 2 + dir) * 2) * 8192 + (size_t)u * 32 + lane;
            g_hbf[hb]        = hh;
            g_hbf[hb + 8192] = hl;
        }

        // ---- per-direction grid barrier (R5: single counter + backoff poll)
        __syncthreads();
        if (tid == 0) {
            asm volatile("red.release.gpu.global.add.u32 [%0], 1;" :: "l"(cnt) : "memory");
            const unsigned target = (unsigned)(s + 1) * 64u;
            unsigned v;
            asm volatile("ld.acquire.gpu.global.u32 %0, [%1];" : "=r"(v) : "l"(cnt) : "memory");
            while (v < target) {
                __nanosleep(32);
                asm volatile("ld.acquire.gpu.global.u32 %0, [%1];" : "=r"(v) : "l"(cnt) : "memory");
            }
        }
        __syncthreads();
        tprev = t;
    }
}

// ---------------- final transpose: out[b][t][c] = hist[t][c][b] --------------
__global__ void __launch_bounds__(256) transpose_out(float* __restrict__ out) {
    __shared__ float S[128 * 33];
    const int t  = blockIdx.x;
    const int c0 = blockIdx.y * 128;
    const int tid = threadIdx.x;

    const float* src = &g_hist[((size_t)t * 512 + c0) * BATCH];
#pragma unroll
    for (int i = 0; i < 4; i++) {
        int idx4 = tid + i * 256;
        float4 v = ((const float4*)src)[idx4];
        int e = idx4 * 4;
        int c = e >> 5, b0 = e & 31;
        float* d = &S[c * 33 + b0];
        d[0] = v.x; d[1] = v.y; d[2] = v.z; d[3] = v.w;
    }
    __syncthreads();

    const int lane = tid & 31;
    const int bq   = tid >> 5;
#pragma unroll
    for (int i = 0; i < 4; i++) {
        int b = bq + i * 8;
        int cc = lane * 4;
        float4 v = make_float4(S[(cc + 0) * 33 + b], S[(cc + 1) * 33 + b],
                               S[(cc + 2) * 33 + b], S[(cc + 3) * 33 + b]);
        *(float4*)&out[((size_t)b * TSEQ + t) * 512 + c0 + cc] = v;
    }
}

// ---------------- entry ------------------------------------------------------
extern "C" void kernel_launch(void* const* d_in, const int* in_sizes, int n_in,
                              void* d_out, int out_size) {
    (void)in_sizes; (void)n_in; (void)out_size;
    const float* x    = (const float*)d_in[0];   // [32,1024,256]
    const float* kern = (const float*)d_in[1];   // [256,2048]
    const float* rk   = (const float*)d_in[2];   // [256,2048]
    float* out = (float*)d_out;                  // [32,1024,512]

    dim3 ggrid(GC / 128, (BATCH * TSEQ) / 128);  // (16, 256)
    gemm_mma<<<ggrid, 256>>>(x, kern);
    blstm_rec<<<128, 256>>>(rk);
    dim3 tgrid(TSEQ, 4);
    transpose_out<<<tgrid, 256>>>(out);
}